// round 14
// baseline (speedup 1.0000x reference)
#include <cuda_runtime.h>
#include <cuda_fp16.h>
#include <cstdint>

#define B_DIM 4096
#define T_DIM 200
#define NEG_INF (-4294967295.0f)
#define NCTA 296
#define KBUF 51200

// smem byte offsets
#define OFF_QH   102400   // f32 qh[32]
#define OFF_W2   102528   // f32 w2[32]
#define OFF_SC   102656   // f32 scores[200] (pad 832)
#define OFF_RED  103488   // f32 red[16]
#define OFF_OP   103552   // float2 opart[8][32]
#define SMEM_BYTES 105600

__device__ float    g_wq[2048];    // W1a + W1c
__device__ uint32_t g_whi[1024];   // f16x2 fused weights, mma B-fragment order
__device__ uint32_t g_wlo[1024];   // f16 residuals

__global__ __launch_bounds__(256)
void setup_kernel(const float* __restrict__ W1)
{
    const int tid = threadIdx.x, blk = blockIdx.x;
    if (blk < 8) {
        const int i = blk * 256 + tid;
        g_wq[i] = W1[i] + W1[4096 + i];
        return;
    }
    const int idx = (blk - 8) * 256 + tid;
    int d2 = idx >> 5, j = idx & 31, k = 2 * d2;
    float w0 = W1[2048 + k * 32 + j] - W1[4096 + k * 32 + j];
    float w1 = W1[2048 + (k + 1) * 32 + j] - W1[4096 + (k + 1) * 32 + j];
    uint32_t hi, lo;
    asm("cvt.rn.f16x2.f32 %0, %1, %2;" : "=r"(hi) : "f"(w1), "f"(w0));
    float h0f = __half2float(__ushort_as_half((unsigned short)(hi & 0xFFFFu)));
    float h1f = __half2float(__ushort_as_half((unsigned short)(hi >> 16)));
    asm("cvt.rn.f16x2.f32 %0, %1, %2;" : "=r"(lo) : "f"(w1 - h1f), "f"(w0 - h0f));
    int ks = d2 >> 3, k2 = d2 & 7, t4 = k2 & 3, sel = k2 >> 2;
    int word = ((ks * 4 + t4) * 32 + j) * 2 + sel;
    g_whi[word] = hi;
    g_wlo[word] = lo;
}

static __device__ __forceinline__ float sigmoidf_fast(float h) {
    return __fdividef(1.0f, 1.0f + __expf(-h));
}

__global__ __launch_bounds__(256, 2)
void attn_pool_kernel(const float* __restrict__ query,
                      const float* __restrict__ keys,
                      const unsigned char* __restrict__ mask_raw,
                      const float* __restrict__ b1,
                      const float* __restrict__ W2,
                      const float* __restrict__ b2,
                      float* __restrict__ out)
{
    extern __shared__ char sm[];
    float* smf = (float*)sm;
    const int tid  = threadIdx.x;
    const int lane = tid & 31;
    const int wid  = tid >> 5;
    const int g    = lane >> 2;
    const int t4   = lane & 3;
    uint32_t sbase;
    asm("{ .reg .u64 t; cvta.to.shared.u64 t, %1; cvt.u32.u64 %0, t; }"
        : "=r"(sbase) : "l"(sm));

    // ---- one-time: mask dtype detect + b2 + w2 ----
    int my_nz = 0;
    #pragma unroll
    for (int w = lane; w < 256; w += 32)
        my_nz |= mask_raw[4 * w + 1] | mask_raw[4 * w + 2] | mask_raw[4 * w + 3];
    const bool mode_u8 = __any_sync(0xffffffffu, my_nz != 0);
    const int* mask_i32 = (const int*)mask_raw;
    const float b2v = __ldg(b2);
    if (wid == 6) smf[OFF_W2 / 4 + lane] = __ldg(W2 + lane);

    // ---- prologue: stage first b into buffer 0 ----
    int b = blockIdx.x;
    {
        const char* src = (const char*)(keys + (size_t)b * 12800);
        #pragma unroll 4
        for (int i = tid; i < 3200; i += 256) {
            int r = i >> 4, c = i & 15;
            asm volatile("cp.async.cg.shared.global [%0], [%1], 16;"
                         :: "r"(sbase + r * 256 + ((c ^ (r & 7)) << 4)),
                            "l"(src + i * 16));
        }
        asm volatile("cp.async.commit_group;" ::: "memory");
    }

    int iter = 0;
    for (; b < B_DIM; b += NCTA, ++iter) {
        const int buf = iter & 1;
        const uint32_t kbase = sbase + buf * KBUF;
        const int bn = b + NCTA;

        // ---- prefetch next b into other buffer ----
        if (bn < B_DIM) {
            const char* src = (const char*)(keys + (size_t)bn * 12800);
            const uint32_t dbase = sbase + (buf ^ 1) * KBUF;
            #pragma unroll 4
            for (int i = tid; i < 3200; i += 256) {
                int r = i >> 4, c = i & 15;
                asm volatile("cp.async.cg.shared.global [%0], [%1], 16;"
                             :: "r"(dbase + r * 256 + ((c ^ (r & 7)) << 4)),
                                "l"(src + i * 16));
            }
            asm volatile("cp.async.commit_group;" ::: "memory");
        }

        // ---- warp 5: qh chain for this b (g_wq L1-resident) ----
        if (wid == 5) {
            float q0 = query[(size_t)b * 64 + lane];
            float q1 = query[(size_t)b * 64 + 32 + lane];
            float s = b1[lane];
            #pragma unroll
            for (int d = 0; d < 32; d++)
                s = fmaf(__shfl_sync(0xffffffffu, q0, d), g_wq[d * 32 + lane], s);
            #pragma unroll
            for (int d = 0; d < 32; d++)
                s = fmaf(__shfl_sync(0xffffffffu, q1, d), g_wq[(32 + d) * 32 + lane], s);
            smf[OFF_QH / 4 + lane] = s;
        }

        // ---- mask bits for this b's tiles ----
        int mval = 0;
        if (t4 == 0) {
            #pragma unroll
            for (int mi = 0; mi < 2; mi++) {
                if (mi == 1 && wid >= 5) continue;
                const int m0 = (wid + 8 * mi) * 16;
                const int r0 = m0 + g, r1 = r0 + 8;
                long gb = (long)b * T_DIM;
                bool v0 = mode_u8 ? (mask_raw[gb + r0] != 0) : (mask_i32[gb + r0] != 0);
                mval |= (int)v0 << (2 * mi);
                if (r1 < T_DIM) {
                    bool v1 = mode_u8 ? (mask_raw[gb + r1] != 0) : (mask_i32[gb + r1] != 0);
                    mval |= (int)v1 << (2 * mi + 1);
                }
            }
        }

        // ---- wait for current buffer (keep the prefetch group in flight) ----
        if (bn < B_DIM) asm volatile("cp.async.wait_group 1;" ::: "memory");
        else           asm volatile("cp.async.wait_group 0;" ::: "memory");
        __syncthreads();

        // ====== score GEMM: m16n8k16 f16; A = fp32 keys (smem, cvt), B = L1 __ldg ======
        float acc[2][4][4];
        #pragma unroll
        for (int mi = 0; mi < 2; mi++)
            #pragma unroll
            for (int nt = 0; nt < 4; nt++)
                #pragma unroll
                for (int e = 0; e < 4; e++) acc[mi][nt][e] = 0.0f;

        const uint32_t wofs = (uint32_t)(t4 * 64 + g * 2);
        #pragma unroll
        for (int ks = 0; ks < 4; ks++) {
            uint2 bh[4], bl[4];
            #pragma unroll
            for (int nt = 0; nt < 4; nt++) {
                bh[nt] = __ldg((const uint2*)(g_whi + wofs + ks * 256 + nt * 16));
                bl[nt] = __ldg((const uint2*)(g_wlo + wofs + ks * 256 + nt * 16));
            }
            const int c0 = 4 * ks + (t4 >> 1);
            const uint32_t o0 = (uint32_t)((c0 ^ g) << 4);
            const uint32_t o2 = (uint32_t)(((c0 + 2) ^ g) << 4);
            #pragma unroll
            for (int mi = 0; mi < 2; mi++) {
                if (mi == 1 && wid >= 5) continue;
                const int m0 = (wid + 8 * mi) * 16;
                const uint32_t base0 = kbase +
                    (uint32_t)((m0 + g) * 256 + ((t4 & 1) << 3));
                float2 A0, A2;
                asm("ld.shared.v2.f32 {%0,%1},[%2];" : "=f"(A0.x), "=f"(A0.y) : "r"(base0 + o0));
                asm("ld.shared.v2.f32 {%0,%1},[%2];" : "=f"(A2.x), "=f"(A2.y) : "r"(base0 + o2));
                uint32_t a0, a1, a2, a3;
                asm("cvt.rn.f16x2.f32 %0,%1,%2;" : "=r"(a0) : "f"(A0.y), "f"(A0.x));
                asm("cvt.rn.f16x2.f32 %0,%1,%2;" : "=r"(a2) : "f"(A2.y), "f"(A2.x));
                if ((m0 + g + 8) < T_DIM) {
                    float2 A1, A3;
                    asm("ld.shared.v2.f32 {%0,%1},[%2];"
                        : "=f"(A1.x), "=f"(A1.y) : "r"(base0 + 2048 + o0));
                    asm("ld.shared.v2.f32 {%0,%1},[%2];"
                        : "=f"(A3.x), "=f"(A3.y) : "r"(base0 + 2048 + o2));
                    asm("cvt.rn.f16x2.f32 %0,%1,%2;" : "=r"(a1) : "f"(A1.y), "f"(A1.x));
                    asm("cvt.rn.f16x2.f32 %0,%1,%2;" : "=r"(a3) : "f"(A3.y), "f"(A3.x));
                } else { a1 = 0u; a3 = 0u; }
                #pragma unroll
                for (int nt = 0; nt < 4; nt++) {
                    asm volatile(
                        "mma.sync.aligned.m16n8k16.row.col.f32.f16.f16.f32 "
                        "{%0,%1,%2,%3}, {%4,%5,%6,%7}, {%8,%9}, {%0,%1,%2,%3};"
                        : "+f"(acc[mi][nt][0]), "+f"(acc[mi][nt][1]),
                          "+f"(acc[mi][nt][2]), "+f"(acc[mi][nt][3])
                        : "r"(a0), "r"(a1), "r"(a2), "r"(a3),
                          "r"(bh[nt].x), "r"(bh[nt].y));
                    asm volatile(
                        "mma.sync.aligned.m16n8k16.row.col.f32.f16.f16.f32 "
                        "{%0,%1,%2,%3}, {%4,%5,%6,%7}, {%8,%9}, {%0,%1,%2,%3};"
                        : "+f"(acc[mi][nt][0]), "+f"(acc[mi][nt][1]),
                          "+f"(acc[mi][nt][2]), "+f"(acc[mi][nt][3])
                        : "r"(a0), "r"(a1), "r"(a2), "r"(a3),
                          "r"(bl[nt].x), "r"(bl[nt].y));
                }
            }
        }

        // ---- epilogue: h = C + qh ; sigmoid; dot W2; reduce over t4; mask ----
        #pragma unroll
        for (int mi = 0; mi < 2; mi++) {
            if (mi == 1 && wid >= 5) continue;
            const int m0 = (wid + 8 * mi) * 16;
            float s_lo = 0.0f, s_hi = 0.0f;
            #pragma unroll
            for (int nt = 0; nt < 4; nt++) {
                const int j0 = 8 * nt + 2 * t4;
                float2 qh2 = *(float2*)(sm + OFF_QH + j0 * 4);
                float2 w22 = *(float2*)(sm + OFF_W2 + j0 * 4);
                s_lo = fmaf(sigmoidf_fast(acc[mi][nt][0] + qh2.x), w22.x, s_lo);
                s_lo = fmaf(sigmoidf_fast(acc[mi][nt][1] + qh2.y), w22.y, s_lo);
                s_hi = fmaf(sigmoidf_fast(acc[mi][nt][2] + qh2.x), w22.x, s_hi);
                s_hi = fmaf(sigmoidf_fast(acc[mi][nt][3] + qh2.y), w22.y, s_hi);
            }
            s_lo += __shfl_xor_sync(0xffffffffu, s_lo, 1);
            s_lo += __shfl_xor_sync(0xffffffffu, s_lo, 2);
            s_hi += __shfl_xor_sync(0xffffffffu, s_hi, 1);
            s_hi += __shfl_xor_sync(0xffffffffu, s_hi, 2);
            if (t4 == 0) {
                const int r0 = m0 + g, r1 = r0 + 8;
                smf[OFF_SC / 4 + r0] = ((mval >> (2 * mi)) & 1) ? (s_lo + b2v) : NEG_INF;
                if (r1 < T_DIM)
                    smf[OFF_SC / 4 + r1] = ((mval >> (2 * mi + 1)) & 1) ? (s_hi + b2v) : NEG_INF;
            }
        }
        __syncthreads();

        // ---- fused online softmax + weighted partial (warp owns scores [25w, 25w+25)) ----
        const int t0 = wid * 25;
        float sc = -1e38f;
        if (lane < 25) sc = smf[OFF_SC / 4 + t0 + lane];
        float lmax = sc;
        #pragma unroll
        for (int o = 16; o; o >>= 1) lmax = fmaxf(lmax, __shfl_xor_sync(0xffffffffu, lmax, o));
        float e = (lane < 25) ? __expf(sc - lmax) : 0.0f;
        float lsum = e;
        #pragma unroll
        for (int o = 16; o; o >>= 1) lsum += __shfl_xor_sync(0xffffffffu, lsum, o);
        if (lane == 0) {
            smf[OFF_RED / 4 + wid] = lmax;
            smf[OFF_RED / 4 + 8 + wid] = lsum;
        }
        // weighted partial from fp32 keys (e broadcast via shfl)
        float ax = 0.0f, ay = 0.0f;
        #pragma unroll 5
        for (int t = 0; t < 25; t++) {
            float p = __shfl_sync(0xffffffffu, e, t);
            const int tt = t0 + t;
            float kx, ky;
            asm("ld.shared.v2.f32 {%0,%1},[%2];"
                : "=f"(kx), "=f"(ky)
                : "r"(kbase + tt * 256 + ((((uint32_t)(lane >> 1)) ^ (tt & 7)) << 4)
                      + ((lane & 1) << 3)));
            ax = fmaf(p, kx, ax);
            ay = fmaf(p, ky, ay);
        }
        __syncthreads();

        // ---- global combine, scale, store partials ----
        {
            float gm = smf[OFF_RED / 4];
            #pragma unroll
            for (int p = 1; p < 8; p++) gm = fmaxf(gm, smf[OFF_RED / 4 + p]);
            float gs = 0.0f;
            #pragma unroll
            for (int p = 0; p < 8; p++)
                gs = fmaf(smf[OFF_RED / 4 + 8 + p], __expf(smf[OFF_RED / 4 + p] - gm), gs);
            float scale = __expf(lmax - gm) * __fdividef(1.0f, gs);
            *(float2*)(sm + OFF_OP + wid * 256 + lane * 8) =
                make_float2(ax * scale, ay * scale);
        }
        __syncthreads();
        if (tid < 64) {
            float r = 0.0f;
            #pragma unroll
            for (int p = 0; p < 8; p++)
                r += smf[(OFF_OP + p * 256) / 4 + tid];
            out[(size_t)b * 64 + tid] = r;
        }
    }
}

extern "C" void kernel_launch(void* const* d_in, const int* in_sizes, int n_in,
                              void* d_out, int out_size)
{
    const float*         query = (const float*)d_in[0];
    const float*         keys  = (const float*)d_in[1];
    const unsigned char* mask  = (const unsigned char*)d_in[2];
    const float*         W1    = (const float*)d_in[3];
    const float*         b1    = (const float*)d_in[4];
    const float*         W2    = (const float*)d_in[5];
    const float*         b2    = (const float*)d_in[6];
    float* out = (float*)d_out;

    setup_kernel<<<12, 256>>>(W1);
    cudaFuncSetAttribute(attn_pool_kernel,
                         cudaFuncAttributeMaxDynamicSharedMemorySize, SMEM_BYTES);
    attn_pool_kernel<<<NCTA, 256, SMEM_BYTES>>>(query, keys, mask, b1, W2, b2, out);
}

// round 15
// speedup vs baseline: 1.2563x; 1.2563x over previous
#include <cuda_runtime.h>
#include <cuda_fp16.h>
#include <cstdint>

#define B_DIM 4096
#define T_DIM 200
#define NEG_INF (-4294967295.0f)
#define KROW 144          // f16 key row stride bytes (36 words; 36 mod 32 = 4)

// smem byte offsets
#define OFF_K    0        // f16 keys, 208 rows x KROW
#define OFF_WT   29952    // weight tables: hi words [0,1152), lo words [1152,2304)
#define OFF_QH   39168    // f32 qh[32]
#define OFF_W2   39296    // f32 w2[32]
#define OFF_SC   39424    // f32 scores[200] (pad 832)
#define OFF_RED  40256    // f32 red[16]
#define OFF_OP   40320    // float2 opart[8][32]
#define SMEM_BYTES 42368

static __device__ __forceinline__ float sigmoidf_fast(float h) {
    return __fdividef(1.0f, 1.0f + __expf(-h));
}

__global__ __launch_bounds__(256, 4)
void attn_pool_kernel(const float* __restrict__ query,
                      const float* __restrict__ keys,
                      const unsigned char* __restrict__ mask_raw,
                      const float* __restrict__ W1,
                      const float* __restrict__ b1,
                      const float* __restrict__ W2,
                      const float* __restrict__ b2,
                      float* __restrict__ out)
{
    extern __shared__ char sm[];
    float* smf = (float*)sm;
    const int b    = blockIdx.x;
    const int tid  = threadIdx.x;
    const int lane = tid & 31;
    const int wid  = tid >> 5;
    const int g    = lane >> 2;
    const int t4   = lane & 3;
    uint32_t sbase;
    asm("{ .reg .u64 t; cvta.to.shared.u64 t, %1; cvt.u32.u64 %0, t; }"
        : "=r"(sbase) : "l"(sm));
    const float4* kb = (const float4*)(keys + (size_t)b * (T_DIM * 64));

    // ---- stage keys: fp32 LDG.128 -> f16x2 -> STS.64, padded rows ----
    #pragma unroll 4
    for (int i = tid; i < T_DIM * 16; i += 256) {
        int r = i >> 4, c = i & 15;
        float4 v = __ldg(kb + i);
        uint32_t p0, p1;
        asm("cvt.rn.f16x2.f32 %0,%1,%2;" : "=r"(p0) : "f"(v.y), "f"(v.x));
        asm("cvt.rn.f16x2.f32 %0,%1,%2;" : "=r"(p1) : "f"(v.w), "f"(v.z));
        asm volatile("st.shared.v2.b32 [%0],{%1,%2};"
                     :: "r"(sbase + OFF_K + r * KROW + c * 8), "r"(p0), "r"(p1));
    }

    // ---- in-CTA weight fragment tables (overlaps key-staging DRAM wait) ----
    #pragma unroll
    for (int idx = tid; idx < 1024; idx += 256) {
        int d2 = idx >> 5, j = idx & 31, k = 2 * d2;
        float wb0 = __ldg(W1 + 2048 + k * 32 + j) - __ldg(W1 + 4096 + k * 32 + j);
        float wb1 = __ldg(W1 + 2048 + (k + 1) * 32 + j) - __ldg(W1 + 4096 + (k + 1) * 32 + j);
        uint32_t hi, lo;
        asm("cvt.rn.f16x2.f32 %0, %1, %2;" : "=r"(hi) : "f"(wb1), "f"(wb0));
        float h0f = __half2float(__ushort_as_half((unsigned short)(hi & 0xFFFFu)));
        float h1f = __half2float(__ushort_as_half((unsigned short)(hi >> 16)));
        asm("cvt.rn.f16x2.f32 %0, %1, %2;" : "=r"(lo) : "f"(wb1 - h1f), "f"(wb0 - h0f));
        int ks = d2 >> 3, k2 = d2 & 7, t4j = k2 & 3, sel = k2 >> 2;
        int word = ks * 288 + t4j * 72 + j * 2 + sel;
        asm volatile("st.shared.b32 [%0],%1;"
                     :: "r"(sbase + OFF_WT + word * 4), "r"(hi));
        asm volatile("st.shared.b32 [%0],%1;"
                     :: "r"(sbase + OFF_WT + 4608 + word * 4), "r"(lo));
    }

    // ---- warp 0: qh directly from W1 ; warp 1: w2 ----
    if (wid == 0) {
        float q0 = __ldg(query + (size_t)b * 64 + lane);
        float q1 = __ldg(query + (size_t)b * 64 + 32 + lane);
        float s = __ldg(b1 + lane);
        #pragma unroll
        for (int d = 0; d < 32; d++) {
            float qd = __shfl_sync(0xffffffffu, q0, d);
            s = fmaf(qd, __ldg(W1 + d * 32 + lane) + __ldg(W1 + (128 + d) * 32 + lane), s);
        }
        #pragma unroll
        for (int d = 0; d < 32; d++) {
            float qd = __shfl_sync(0xffffffffu, q1, d);
            s = fmaf(qd, __ldg(W1 + (32 + d) * 32 + lane) + __ldg(W1 + (160 + d) * 32 + lane), s);
        }
        smf[OFF_QH / 4 + lane] = s;
    }
    if (wid == 1) smf[OFF_W2 / 4 + lane] = __ldg(W2 + lane);

    // ---- mask dtype detect + per-tile mask bits + b2 ----
    int my_nz = 0;
    #pragma unroll
    for (int w = lane; w < 256; w += 32)
        my_nz |= mask_raw[4 * w + 1] | mask_raw[4 * w + 2] | mask_raw[4 * w + 3];
    const bool mode_u8 = __any_sync(0xffffffffu, my_nz != 0);
    const int* mask_i32 = (const int*)mask_raw;
    const float b2v = __ldg(b2);

    int mval = 0;
    if (t4 == 0) {
        #pragma unroll
        for (int mi = 0; mi < 2; mi++) {
            if (mi == 1 && wid >= 5) continue;
            const int m0 = (wid + 8 * mi) * 16;
            const int r0 = m0 + g, r1 = r0 + 8;
            bool v0 = mode_u8 ? (mask_raw[b * T_DIM + r0] != 0)
                              : (mask_i32[b * T_DIM + r0] != 0);
            mval |= (int)v0 << (2 * mi);
            if (r1 < T_DIM) {
                bool v1 = mode_u8 ? (mask_raw[b * T_DIM + r1] != 0)
                                  : (mask_i32[b * T_DIM + r1] != 0);
                mval |= (int)v1 << (2 * mi + 1);
            }
        }
    }

    __syncthreads();

    // ====== score GEMM: m16n8k16 f16; A = f16 keys (smem), B = smem tables ======
    float acc[2][4][4];
    #pragma unroll
    for (int mi = 0; mi < 2; mi++)
        #pragma unroll
        for (int nt = 0; nt < 4; nt++)
            #pragma unroll
            for (int e = 0; e < 4; e++) acc[mi][nt][e] = 0.0f;

    #pragma unroll
    for (int ks = 0; ks < 4; ks++) {
        const uint32_t wrow = sbase + OFF_WT + (uint32_t)(ks * 1152 + t4 * 288 + g * 8);
        uint2 bh[4], bl[4];
        #pragma unroll
        for (int nt = 0; nt < 4; nt++) {
            asm("ld.shared.v2.u32 {%0,%1},[%2];"
                : "=r"(bh[nt].x), "=r"(bh[nt].y) : "r"(wrow + nt * 64));
            asm("ld.shared.v2.u32 {%0,%1},[%2];"
                : "=r"(bl[nt].x), "=r"(bl[nt].y) : "r"(wrow + nt * 64 + 4608));
        }
        #pragma unroll
        for (int mi = 0; mi < 2; mi++) {
            if (mi == 1 && wid >= 5) continue;
            const int m0 = (wid + 8 * mi) * 16;
            const uint32_t abase = sbase + OFF_K +
                                   (uint32_t)((m0 + g) * KROW + ks * 32 + t4 * 4);
            uint32_t a0, a1, a2, a3;
            asm("ld.shared.b32 %0,[%1];" : "=r"(a0) : "r"(abase));
            asm("ld.shared.b32 %0,[%1];" : "=r"(a2) : "r"(abase + 16));
            if ((m0 + g + 8) < T_DIM) {
                asm("ld.shared.b32 %0,[%1];" : "=r"(a1) : "r"(abase + 8 * KROW));
                asm("ld.shared.b32 %0,[%1];" : "=r"(a3) : "r"(abase + 8 * KROW + 16));
            } else { a1 = 0u; a3 = 0u; }
            #pragma unroll
            for (int nt = 0; nt < 4; nt++) {
                asm volatile(
                    "mma.sync.aligned.m16n8k16.row.col.f32.f16.f16.f32 "
                    "{%0,%1,%2,%3}, {%4,%5,%6,%7}, {%8,%9}, {%0,%1,%2,%3};"
                    : "+f"(acc[mi][nt][0]), "+f"(acc[mi][nt][1]),
                      "+f"(acc[mi][nt][2]), "+f"(acc[mi][nt][3])
                    : "r"(a0), "r"(a1), "r"(a2), "r"(a3),
                      "r"(bh[nt].x), "r"(bh[nt].y));
                asm volatile(
                    "mma.sync.aligned.m16n8k16.row.col.f32.f16.f16.f32 "
                    "{%0,%1,%2,%3}, {%4,%5,%6,%7}, {%8,%9}, {%0,%1,%2,%3};"
                    : "+f"(acc[mi][nt][0]), "+f"(acc[mi][nt][1]),
                      "+f"(acc[mi][nt][2]), "+f"(acc[mi][nt][3])
                    : "r"(a0), "r"(a1), "r"(a2), "r"(a3),
                      "r"(bl[nt].x), "r"(bl[nt].y));
            }
        }
    }

    // ---- epilogue: h = C + qh ; sigmoid; dot W2; reduce over t4; mask ----
    #pragma unroll
    for (int mi = 0; mi < 2; mi++) {
        if (mi == 1 && wid >= 5) continue;
        const int m0 = (wid + 8 * mi) * 16;
        float s_lo = 0.0f, s_hi = 0.0f;
        #pragma unroll
        for (int nt = 0; nt < 4; nt++) {
            const int j0 = 8 * nt + 2 * t4;
            float2 qh2 = *(float2*)(sm + OFF_QH + j0 * 4);
            float2 w22 = *(float2*)(sm + OFF_W2 + j0 * 4);
            s_lo = fmaf(sigmoidf_fast(acc[mi][nt][0] + qh2.x), w22.x, s_lo);
            s_lo = fmaf(sigmoidf_fast(acc[mi][nt][1] + qh2.y), w22.y, s_lo);
            s_hi = fmaf(sigmoidf_fast(acc[mi][nt][2] + qh2.x), w22.x, s_hi);
            s_hi = fmaf(sigmoidf_fast(acc[mi][nt][3] + qh2.y), w22.y, s_hi);
        }
        s_lo += __shfl_xor_sync(0xffffffffu, s_lo, 1);
        s_lo += __shfl_xor_sync(0xffffffffu, s_lo, 2);
        s_hi += __shfl_xor_sync(0xffffffffu, s_hi, 1);
        s_hi += __shfl_xor_sync(0xffffffffu, s_hi, 2);
        if (t4 == 0) {
            const int r0 = m0 + g, r1 = r0 + 8;
            smf[OFF_SC / 4 + r0] = ((mval >> (2 * mi)) & 1) ? (s_lo + b2v) : NEG_INF;
            if (r1 < T_DIM)
                smf[OFF_SC / 4 + r1] = ((mval >> (2 * mi + 1)) & 1) ? (s_hi + b2v) : NEG_INF;
        }
    }
    __syncthreads();

    // ---- fused online softmax + weighted partial (warp owns scores [25w, 25w+25)) ----
    const int t0 = wid * 25;
    float sc = (lane < 25) ? smf[OFF_SC / 4 + t0 + lane] : -1e38f;
    float lmax = sc;
    #pragma unroll
    for (int o = 16; o; o >>= 1) lmax = fmaxf(lmax, __shfl_xor_sync(0xffffffffu, lmax, o));
    float e = (lane < 25) ? __expf(sc - lmax) : 0.0f;
    float lsum = e;
    #pragma unroll
    for (int o = 16; o; o >>= 1) lsum += __shfl_xor_sync(0xffffffffu, lsum, o);
    if (lane == 0) {
        smf[OFF_RED / 4 + wid] = lmax;
        smf[OFF_RED / 4 + 8 + wid] = lsum;
    }
    // weighted partial from f16 smem keys; lane owns d-pair (2lane, 2lane+1)
    float ax = 0.0f, ay = 0.0f;
    #pragma unroll 5
    for (int t = 0; t < 25; t++) {
        float p = __shfl_sync(0xffffffffu, e, t);
        uint32_t kv;
        asm("ld.shared.b32 %0,[%1];" : "=r"(kv)
            : "r"(sbase + OFF_K + (t0 + t) * KROW + lane * 4));
        float kx, ky;
        asm("{ .reg .b16 l, h; mov.b32 {l,h}, %2; cvt.f32.f16 %0, l; cvt.f32.f16 %1, h; }"
            : "=f"(kx), "=f"(ky) : "r"(kv));
        ax = fmaf(p, kx, ax);
        ay = fmaf(p, ky, ay);
    }
    __syncthreads();

    // ---- global combine: correct partials by exp(lmax-gm)/gs, store ----
    {
        float gm = smf[OFF_RED / 4];
        #pragma unroll
        for (int p = 1; p < 8; p++) gm = fmaxf(gm, smf[OFF_RED / 4 + p]);
        float gs = 0.0f;
        #pragma unroll
        for (int p = 0; p < 8; p++)
            gs = fmaf(smf[OFF_RED / 4 + 8 + p], __expf(smf[OFF_RED / 4 + p] - gm), gs);
        float scale = __expf(lmax - gm) * __fdividef(1.0f, gs);
        *(float2*)(sm + OFF_OP + wid * 256 + lane * 8) =
            make_float2(ax * scale, ay * scale);
    }
    __syncthreads();
    if (tid < 64) {
        float r = 0.0f;
        #pragma unroll
        for (int p = 0; p < 8; p++)
            r += smf[(OFF_OP + p * 256) / 4 + tid];
        out[(size_t)b * 64 + tid] = r;
    }
}

extern "C" void kernel_launch(void* const* d_in, const int* in_sizes, int n_in,
                              void* d_out, int out_size)
{
    const float*         query = (const float*)d_in[0];
    const float*         keys  = (const float*)d_in[1];
    const unsigned char* mask  = (const unsigned char*)d_in[2];
    const float*         W1    = (const float*)d_in[3];
    const float*         b1    = (const float*)d_in[4];
    const float*         W2    = (const float*)d_in[5];
    const float*         b2    = (const float*)d_in[6];
    float* out = (float*)d_out;

    cudaFuncSetAttribute(attn_pool_kernel,
                         cudaFuncAttributeMaxDynamicSharedMemorySize, SMEM_BYTES);
    attn_pool_kernel<<<B_DIM, 256, SMEM_BYTES>>>(query, keys, mask, W1, b1, W2, b2, out);
}

// round 16
// speedup vs baseline: 1.3440x; 1.0698x over previous
#include <cuda_runtime.h>
#include <cuda_fp16.h>
#include <cstdint>

#define B_DIM 4096
#define T_DIM 200
#define NEG_INF (-4294967295.0f)
#define KROW 144          // f16 key row stride bytes (36 words; 36 mod 32 = 4)

// smem byte offsets
#define OFF_K    0        // f16 keys, 200 x KROW
#define OFF_WT   28800    // staged weight tables: hi[1152 w] + lo[1152 w]
#define OFF_QH   38016    // f32 qh[32]
#define OFF_W2   38144    // f32 w2[32]
#define OFF_SC   38272    // f32 scores[200] (pad 832)
#define OFF_RED  39104    // f32 red[16]
#define OFF_OP   39168    // float2 opart[8][32]
#define SMEM_BYTES 41216

__device__ float    g_wq[2048];    // W1a + W1c
__device__ uint32_t g_wtab[2304];  // [0,1152): f16x2 hi fragments; [1152,2304): lo
__device__ int      g_mode;        // 1 = mask is u8, 0 = int32

__global__ __launch_bounds__(256)
void setup_kernel(const float* __restrict__ W1,
                  const unsigned char* __restrict__ mask_raw)
{
    const int tid = threadIdx.x, blk = blockIdx.x;
    if (blk < 8) {
        const int i = blk * 256 + tid;
        g_wq[i] = W1[i] + W1[4096 + i];
        return;
    }
    if (blk == 12) {
        // mask dtype detection: int32 {0,1} has zero high bytes in first 256 words
        const uint32_t* mw = (const uint32_t*)mask_raw;
        uint32_t nz = mw[tid] & 0xFFFFFF00u;
        __shared__ int any_nz;
        if (tid == 0) any_nz = 0;
        __syncthreads();
        if (__syncthreads_or(nz != 0)) { if (tid == 0) g_mode = 1; }
        else                           { if (tid == 0) g_mode = 0; }
        return;
    }
    const int idx = (blk - 8) * 256 + tid;
    int d2 = idx >> 5, j = idx & 31, k = 2 * d2;
    float w0 = W1[2048 + k * 32 + j] - W1[4096 + k * 32 + j];
    float w1 = W1[2048 + (k + 1) * 32 + j] - W1[4096 + (k + 1) * 32 + j];
    uint32_t hi, lo;
    asm("cvt.rn.f16x2.f32 %0, %1, %2;" : "=r"(hi) : "f"(w1), "f"(w0));
    float h0f = __half2float(__ushort_as_half((unsigned short)(hi & 0xFFFFu)));
    float h1f = __half2float(__ushort_as_half((unsigned short)(hi >> 16)));
    asm("cvt.rn.f16x2.f32 %0, %1, %2;" : "=r"(lo) : "f"(w1 - h1f), "f"(w0 - h0f));
    int ks = d2 >> 3, k2 = d2 & 7, t4 = k2 & 3, sel = k2 >> 2;
    // padded fragment layout: t4 stride 72 words, ks stride 288 words
    int word = ks * 288 + t4 * 72 + j * 2 + sel;
    g_wtab[word]        = hi;
    g_wtab[1152 + word] = lo;
}

static __device__ __forceinline__ float sigmoidf_fast(float h) {
    return __fdividef(1.0f, 1.0f + __expf(-h));
}

__global__ __launch_bounds__(256, 4)
void attn_pool_kernel(const float* __restrict__ query,
                      const float* __restrict__ keys,
                      const unsigned char* __restrict__ mask_raw,
                      const float* __restrict__ b1,
                      const float* __restrict__ W2,
                      const float* __restrict__ b2,
                      float* __restrict__ out)
{
    extern __shared__ char sm[];
    float* smf = (float*)sm;
    const int b    = blockIdx.x;
    const int tid  = threadIdx.x;
    const int lane = tid & 31;
    const int wid  = tid >> 5;
    const int g    = lane >> 2;
    const int t4   = lane & 3;
    uint32_t sbase;
    asm("{ .reg .u64 t; cvta.to.shared.u64 t, %1; cvt.u32.u64 %0, t; }"
        : "=r"(sbase) : "l"(sm));
    const float* kb = keys + (size_t)b * (T_DIM * 64);

    // ---- stage weight tables via cp.async (L2-hot) ----
    for (int i = tid; i < 576; i += 256)
        asm volatile("cp.async.cg.shared.global [%0], [%1], 16;"
                     :: "r"(sbase + OFF_WT + i * 16), "l"((const char*)g_wtab + i * 16));
    asm volatile("cp.async.commit_group;" ::: "memory");

    // ---- stage keys: fp32 LDG.128 -> f16x2 -> STS.64, padded rows ----
    #pragma unroll 4
    for (int i = tid; i < T_DIM * 16; i += 256) {
        int r = i >> 4, c = i & 15;
        float4 v = __ldg((const float4*)kb + i);
        uint32_t p0, p1;
        asm("cvt.rn.f16x2.f32 %0,%1,%2;" : "=r"(p0) : "f"(v.y), "f"(v.x));
        asm("cvt.rn.f16x2.f32 %0,%1,%2;" : "=r"(p1) : "f"(v.w), "f"(v.z));
        asm volatile("st.shared.v2.b32 [%0],{%1,%2};"
                     :: "r"(sbase + OFF_K + r * KROW + c * 8), "r"(p0), "r"(p1));
    }

    // ---- warp 0: qh chain ; warp 1: w2 ----
    if (wid == 0) {
        float q0 = query[b * 64 + lane];
        float q1 = query[b * 64 + 32 + lane];
        float s = b1[lane];
        #pragma unroll
        for (int d = 0; d < 32; d++)
            s = fmaf(__shfl_sync(0xffffffffu, q0, d), g_wq[d * 32 + lane], s);
        #pragma unroll
        for (int d = 0; d < 32; d++)
            s = fmaf(__shfl_sync(0xffffffffu, q1, d), g_wq[(32 + d) * 32 + lane], s);
        smf[OFF_QH / 4 + lane] = s;
    }
    if (wid == 1) smf[OFF_W2 / 4 + lane] = __ldg(W2 + lane);

    // ---- mask mode (precomputed) + per-tile mask bits + b2 ----
    const bool mode_u8 = (g_mode != 0);
    const int* mask_i32 = (const int*)mask_raw;
    const float b2v = __ldg(b2);

    int mval = 0;
    if (t4 == 0) {
        #pragma unroll
        for (int mi = 0; mi < 2; mi++) {
            if (mi == 1 && wid >= 5) continue;
            const int m0 = (wid + 8 * mi) * 16;
            const int r0 = m0 + g, r1 = r0 + 8;
            bool v0 = mode_u8 ? (mask_raw[b * T_DIM + r0] != 0)
                              : (mask_i32[b * T_DIM + r0] != 0);
            mval |= (int)v0 << (2 * mi);
            if (r1 < T_DIM) {
                bool v1 = mode_u8 ? (mask_raw[b * T_DIM + r1] != 0)
                                  : (mask_i32[b * T_DIM + r1] != 0);
                mval |= (int)v1 << (2 * mi + 1);
            }
        }
    }

    asm volatile("cp.async.wait_group 0;" ::: "memory");
    __syncthreads();

    // ====== score GEMM: m16n8k16 f16; A = f16 keys (smem), B = smem tables ======
    float acc[2][4][4];
    #pragma unroll
    for (int mi = 0; mi < 2; mi++)
        #pragma unroll
        for (int nt = 0; nt < 4; nt++)
            #pragma unroll
            for (int e = 0; e < 4; e++) acc[mi][nt][e] = 0.0f;

    #pragma unroll
    for (int ks = 0; ks < 4; ks++) {
        const uint32_t wrow = sbase + OFF_WT + (uint32_t)(ks * 1152 + t4 * 288 + g * 8);
        uint2 bh[4], bl[4];
        #pragma unroll
        for (int nt = 0; nt < 4; nt++) {
            asm("ld.shared.v2.u32 {%0,%1},[%2];"
                : "=r"(bh[nt].x), "=r"(bh[nt].y) : "r"(wrow + nt * 64));
            asm("ld.shared.v2.u32 {%0,%1},[%2];"
                : "=r"(bl[nt].x), "=r"(bl[nt].y) : "r"(wrow + nt * 64 + 4608));
        }
        #pragma unroll
        for (int mi = 0; mi < 2; mi++) {
            if (mi == 1 && wid >= 5) continue;
            const int m0 = (wid + 8 * mi) * 16;
            const uint32_t abase = sbase + OFF_K +
                                   (uint32_t)((m0 + g) * KROW + ks * 32 + t4 * 4);
            uint32_t a0, a1, a2, a3;
            asm("ld.shared.b32 %0,[%1];" : "=r"(a0) : "r"(abase));
            asm("ld.shared.b32 %0,[%1];" : "=r"(a2) : "r"(abase + 16));
            if ((m0 + g + 8) < T_DIM) {
                asm("ld.shared.b32 %0,[%1];" : "=r"(a1) : "r"(abase + 8 * KROW));
                asm("ld.shared.b32 %0,[%1];" : "=r"(a3) : "r"(abase + 8 * KROW + 16));
            } else { a1 = 0u; a3 = 0u; }
            #pragma unroll
            for (int nt = 0; nt < 4; nt++) {
                asm volatile(
                    "mma.sync.aligned.m16n8k16.row.col.f32.f16.f16.f32 "
                    "{%0,%1,%2,%3}, {%4,%5,%6,%7}, {%8,%9}, {%0,%1,%2,%3};"
                    : "+f"(acc[mi][nt][0]), "+f"(acc[mi][nt][1]),
                      "+f"(acc[mi][nt][2]), "+f"(acc[mi][nt][3])
                    : "r"(a0), "r"(a1), "r"(a2), "r"(a3),
                      "r"(bh[nt].x), "r"(bh[nt].y));
                asm volatile(
                    "mma.sync.aligned.m16n8k16.row.col.f32.f16.f16.f32 "
                    "{%0,%1,%2,%3}, {%4,%5,%6,%7}, {%8,%9}, {%0,%1,%2,%3};"
                    : "+f"(acc[mi][nt][0]), "+f"(acc[mi][nt][1]),
                      "+f"(acc[mi][nt][2]), "+f"(acc[mi][nt][3])
                    : "r"(a0), "r"(a1), "r"(a2), "r"(a3),
                      "r"(bl[nt].x), "r"(bl[nt].y));
            }
        }
    }

    // ---- epilogue: h = C + qh ; sigmoid; dot W2; reduce over t4; mask ----
    #pragma unroll
    for (int mi = 0; mi < 2; mi++) {
        if (mi == 1 && wid >= 5) continue;
        const int m0 = (wid + 8 * mi) * 16;
        float s_lo = 0.0f, s_hi = 0.0f;
        #pragma unroll
        for (int nt = 0; nt < 4; nt++) {
            const int j0 = 8 * nt + 2 * t4;
            float2 qh2 = *(float2*)(sm + OFF_QH + j0 * 4);
            float2 w22 = *(float2*)(sm + OFF_W2 + j0 * 4);
            s_lo = fmaf(sigmoidf_fast(acc[mi][nt][0] + qh2.x), w22.x, s_lo);
            s_lo = fmaf(sigmoidf_fast(acc[mi][nt][1] + qh2.y), w22.y, s_lo);
            s_hi = fmaf(sigmoidf_fast(acc[mi][nt][2] + qh2.x), w22.x, s_hi);
            s_hi = fmaf(sigmoidf_fast(acc[mi][nt][3] + qh2.y), w22.y, s_hi);
        }
        s_lo += __shfl_xor_sync(0xffffffffu, s_lo, 1);
        s_lo += __shfl_xor_sync(0xffffffffu, s_lo, 2);
        s_hi += __shfl_xor_sync(0xffffffffu, s_hi, 1);
        s_hi += __shfl_xor_sync(0xffffffffu, s_hi, 2);
        if (t4 == 0) {
            const int r0 = m0 + g, r1 = r0 + 8;
            smf[OFF_SC / 4 + r0] = ((mval >> (2 * mi)) & 1) ? (s_lo + b2v) : NEG_INF;
            if (r1 < T_DIM)
                smf[OFF_SC / 4 + r1] = ((mval >> (2 * mi + 1)) & 1) ? (s_hi + b2v) : NEG_INF;
        }
    }
    __syncthreads();

    // ---- fused online softmax + weighted partial (warp owns scores [25w, 25w+25)) ----
    const int t0 = wid * 25;
    float sc = (lane < 25) ? smf[OFF_SC / 4 + t0 + lane] : -1e38f;
    float lmax = sc;
    #pragma unroll
    for (int o = 16; o; o >>= 1) lmax = fmaxf(lmax, __shfl_xor_sync(0xffffffffu, lmax, o));
    float e = (lane < 25) ? __expf(sc - lmax) : 0.0f;
    float lsum = e;
    #pragma unroll
    for (int o = 16; o; o >>= 1) lsum += __shfl_xor_sync(0xffffffffu, lsum, o);
    if (lane == 0) {
        smf[OFF_RED / 4 + wid] = lmax;
        smf[OFF_RED / 4 + 8 + wid] = lsum;
    }
    // weighted partial from f16 smem keys; lane owns d-pair (2lane, 2lane+1)
    float ax = 0.0f, ay = 0.0f;
    #pragma unroll 5
    for (int t = 0; t < 25; t++) {
        float p = __shfl_sync(0xffffffffu, e, t);
        uint32_t kv;
        asm("ld.shared.b32 %0,[%1];" : "=r"(kv)
            : "r"(sbase + OFF_K + (t0 + t) * KROW + lane * 4));
        float kx, ky;
        asm("{ .reg .b16 l, h; mov.b32 {l,h}, %2; cvt.f32.f16 %0, l; cvt.f32.f16 %1, h; }"
            : "=f"(kx), "=f"(ky) : "r"(kv));
        ax = fmaf(p, kx, ax);
        ay = fmaf(p, ky, ay);
    }
    __syncthreads();

    // ---- global combine: correct partials by exp(lmax-gm)/gs, store ----
    {
        float gm = smf[OFF_RED / 4];
        #pragma unroll
        for (int p = 1; p < 8; p++) gm = fmaxf(gm, smf[OFF_RED / 4 + p]);
        float gs = 0.0f;
        #pragma unroll
        for (int p = 0; p < 8; p++)
            gs = fmaf(smf[OFF_RED / 4 + 8 + p], __expf(smf[OFF_RED / 4 + p] - gm), gs);
        float scale = __expf(lmax - gm) * __fdividef(1.0f, gs);
        *(float2*)(sm + OFF_OP + wid * 256 + lane * 8) =
            make_float2(ax * scale, ay * scale);
    }
    __syncthreads();
    if (tid < 64) {
        float r = 0.0f;
        #pragma unroll
        for (int p = 0; p < 8; p++)
            r += smf[(OFF_OP + p * 256) / 4 + tid];
        out[(size_t)b * 64 + tid] = r;
    }
}

extern "C" void kernel_launch(void* const* d_in, const int* in_sizes, int n_in,
                              void* d_out, int out_size)
{
    const float*         query = (const float*)d_in[0];
    const float*         keys  = (const float*)d_in[1];
    const unsigned char* mask  = (const unsigned char*)d_in[2];
    const float*         W1    = (const float*)d_in[3];
    const float*         b1    = (const float*)d_in[4];
    const float*         W2    = (const float*)d_in[5];
    const float*         b2    = (const float*)d_in[6];
    float* out = (float*)d_out;

    setup_kernel<<<13, 256>>>(W1, mask);
    cudaFuncSetAttribute(attn_pool_kernel,
                         cudaFuncAttributeMaxDynamicSharedMemorySize, SMEM_BYTES);
    attn_pool_kernel<<<B_DIM, 256, SMEM_BYTES>>>(query, keys, mask, b1, W2, b2, out);
}